// round 2
// baseline (speedup 1.0000x reference)
#include <cuda_runtime.h>
#include <cuda_bf16.h>
#include <math.h>

// Problem constants
#define T_STEPS   8192
#define N_RES     2048
#define D_IN      64
#define D_OUT     64
#define LEAK      0.3f
#define NOISE_LVL 0.01f

// Persistent kernel geometry
#define GRID_P    128            // CTAs (<=148 SMs -> all resident)
#define THREADS_P 512
#define ROWS_CTA  16             // rows of W per CTA (128*16 = 2048)
#define K_EXT     2176           // 2048 (W) + 64 (W_in) + 64 zero pad ; = 128*17
#define K_SLICE   17             // elements per thread along k

// Device scratch (allowed: static __device__ globals, no runtime alloc)
__device__ float        g_states[(size_t)T_STEPS * N_RES];  // 64 MB
__device__ float        g_s[2][N_RES];                      // double-buffered state
__device__ unsigned int g_ctr;                              // global barrier counter

// ---------------------------------------------------------------------------
__global__ void init_kernel() {
    int i = blockIdx.x * blockDim.x + threadIdx.x;
    if (i < N_RES) g_s[0][i] = 0.0f;
    if (i == 0)    g_ctr = 0u;
}

// ---------------------------------------------------------------------------
__device__ __forceinline__ unsigned int ld_acquire(const unsigned int* p) {
    unsigned int v;
    asm volatile("ld.acquire.gpu.global.u32 %0, [%1];" : "=r"(v) : "l"(p) : "memory");
    return v;
}

__global__ void __launch_bounds__(THREADS_P, 1)
reservoir_kernel(const float* __restrict__ u,
                 const float* __restrict__ noise,
                 const float* __restrict__ W_in,
                 const float* __restrict__ W)
{
    __shared__ float s_ext[K_EXT];       // [0,2048): s ; [2048,2112): u[t] ; rest 0
    __shared__ float psum[ROWS_CTA][4];  // partial dot sums per row per warp-in-group

    const int tid  = threadIdx.x;
    const int lane = tid & 31;
    const int wid  = tid >> 5;           // 0..15
    const int wig  = wid & 3;            // warp within 4-warp row group
    const int kt   = tid & 127;          // k-lane 0..127
    const int rg   = tid >> 7;           // row group 0..3
    const int rbase = blockIdx.x * ROWS_CTA + rg * 4;

    // ---- Load W slice into registers: 4 rows x 17 k-elements per thread ----
    float w0[K_SLICE], w1[K_SLICE], w2[K_SLICE], w3[K_SLICE];
#pragma unroll
    for (int i = 0; i < K_SLICE; ++i) {
        const int k = kt + 128 * i;
        float a, b, c, d;
        if (k < N_RES) {
            a = W[(size_t)(rbase + 0) * N_RES + k];
            b = W[(size_t)(rbase + 1) * N_RES + k];
            c = W[(size_t)(rbase + 2) * N_RES + k];
            d = W[(size_t)(rbase + 3) * N_RES + k];
        } else if (k < N_RES + D_IN) {
            const int kk = k - N_RES;
            a = W_in[(rbase + 0) * D_IN + kk];
            b = W_in[(rbase + 1) * D_IN + kk];
            c = W_in[(rbase + 2) * D_IN + kk];
            d = W_in[(rbase + 3) * D_IN + kk];
        } else {
            a = b = c = d = 0.0f;
        }
        w0[i] = a; w1[i] = b; w2[i] = c; w3[i] = d;
    }

    // zero the pad region of s_ext once
    if (tid < 64) s_ext[2112 + tid] = 0.0f;

    for (int t = 0; t < T_STEPS; ++t) {
        // ---- stage s (coherent L2 read) + u[t] into shared ----
        {
            const float4 sv = __ldcg((const float4*)&g_s[t & 1][tid * 4]);
            *(float4*)&s_ext[tid * 4] = sv;
            if (tid < 16) {
                const float4 uv = *(const float4*)&u[(size_t)t * D_IN + tid * 4];
                *(float4*)&s_ext[2048 + tid * 4] = uv;
            }
        }
        __syncthreads();

        // ---- 4-row dot-product slice ----
        float a0 = 0.f, a1 = 0.f, a2 = 0.f, a3 = 0.f;
#pragma unroll
        for (int i = 0; i < K_SLICE; ++i) {
            const float x = s_ext[kt + 128 * i];
            a0 = fmaf(w0[i], x, a0);
            a1 = fmaf(w1[i], x, a1);
            a2 = fmaf(w2[i], x, a2);
            a3 = fmaf(w3[i], x, a3);
        }
        // warp reduction
#pragma unroll
        for (int off = 16; off > 0; off >>= 1) {
            a0 += __shfl_xor_sync(0xffffffffu, a0, off);
            a1 += __shfl_xor_sync(0xffffffffu, a1, off);
            a2 += __shfl_xor_sync(0xffffffffu, a2, off);
            a3 += __shfl_xor_sync(0xffffffffu, a3, off);
        }
        if (lane == 0) {
            const int rl = (wid >> 2) * 4;
            psum[rl + 0][wig] = a0;
            psum[rl + 1][wig] = a1;
            psum[rl + 2][wig] = a2;
            psum[rl + 3][wig] = a3;
        }
        __syncthreads();

        // ---- finalize 16 rows: tanh + leak, write next state + trace ----
        if (tid < ROWS_CTA) {
            const float dot = psum[tid][0] + psum[tid][1] + psum[tid][2] + psum[tid][3];
            const int   r   = blockIdx.x * ROWS_CTA + tid;
            const float ns  = tanhf(dot + NOISE_LVL * noise[(size_t)t * N_RES + r]);
            const float sp  = s_ext[r];
            const float sn  = (1.0f - LEAK) * sp + LEAK * ns;
            g_s[(t + 1) & 1][r] = sn;
            g_states[(size_t)t * N_RES + r] = sn;
            __threadfence();   // make this thread's state writes globally visible
        }
        __syncthreads();

        // ---- global barrier: release-arrive + acquire-poll ----
        if (tid == 0) {
            atomicAdd(&g_ctr, 1u);
            const unsigned int target = (unsigned int)(t + 1) * GRID_P;
            while (ld_acquire(&g_ctr) < target) { /* spin on L2 */ }
        }
        __syncthreads();
    }
}

// ---------------------------------------------------------------------------
// Readout: out[T, 64] = states[T, 2048] @ w_out[64, 2048]^T + b_out
__global__ void __launch_bounds__(256)
readout_kernel(const float* __restrict__ wout,
               const float* __restrict__ bout,
               float* __restrict__ out)
{
    __shared__ float As[64][65];  // As[kk][tt] = states[t0+tt][k0+kk]
    __shared__ float Bs[64][65];  // Bs[kk][dd] = w_out[dd][k0+kk]

    const int t0  = blockIdx.x * 64;
    const int tid = threadIdx.x;
    const int tx  = tid & 15;     // d group (4 cols)
    const int ty  = tid >> 4;     // t group (4 rows)

    float acc[4][4];
#pragma unroll
    for (int i = 0; i < 4; ++i)
#pragma unroll
        for (int j = 0; j < 4; ++j) acc[i][j] = 0.0f;

    for (int k0 = 0; k0 < N_RES; k0 += 64) {
#pragma unroll
        for (int i = tid; i < 1024; i += 256) {
            const int r  = i >> 4;          // 0..63
            const int c4 = (i & 15) * 4;    // 0..60
            const float4 v = *(const float4*)&g_states[(size_t)(t0 + r) * N_RES + k0 + c4];
            As[c4 + 0][r] = v.x; As[c4 + 1][r] = v.y;
            As[c4 + 2][r] = v.z; As[c4 + 3][r] = v.w;
            const float4 w = *(const float4*)&wout[(size_t)r * N_RES + k0 + c4];
            Bs[c4 + 0][r] = w.x; Bs[c4 + 1][r] = w.y;
            Bs[c4 + 2][r] = w.z; Bs[c4 + 3][r] = w.w;
        }
        __syncthreads();

#pragma unroll
        for (int kk = 0; kk < 64; ++kk) {
            float a[4], b[4];
#pragma unroll
            for (int j = 0; j < 4; ++j) { a[j] = As[kk][4 * ty + j]; b[j] = Bs[kk][4 * tx + j]; }
#pragma unroll
            for (int i = 0; i < 4; ++i)
#pragma unroll
                for (int j = 0; j < 4; ++j) acc[i][j] = fmaf(a[i], b[j], acc[i][j]);
        }
        __syncthreads();
    }

#pragma unroll
    for (int i = 0; i < 4; ++i)
#pragma unroll
        for (int j = 0; j < 4; ++j)
            out[(size_t)(t0 + 4 * ty + i) * D_OUT + 4 * tx + j] = acc[i][j] + bout[4 * tx + j];
}

// ---------------------------------------------------------------------------
extern "C" void kernel_launch(void* const* d_in, const int* in_sizes, int n_in,
                              void* d_out, int out_size)
{
    const float* u     = (const float*)d_in[0];
    const float* noise = (const float*)d_in[1];
    const float* W_in  = (const float*)d_in[2];
    const float* W     = (const float*)d_in[3];
    const float* w_out = (const float*)d_in[4];
    const float* b_out = (const float*)d_in[5];
    float*       out   = (float*)d_out;

    init_kernel<<<8, 256>>>();
    reservoir_kernel<<<GRID_P, THREADS_P>>>(u, noise, W_in, W);
    readout_kernel<<<T_STEPS / 64, 256>>>(w_out, b_out, out);
}

// round 3
// speedup vs baseline: 1.1507x; 1.1507x over previous
#include <cuda_runtime.h>
#include <cuda_bf16.h>
#include <math.h>

// Problem constants
#define T_STEPS   8192
#define N_RES     2048
#define D_IN      64
#define D_OUT     64
#define LEAK      0.3f
#define NOISE_LVL 0.01f

// Persistent kernel geometry
#define GRID_P    128            // CTAs (<=148 SMs -> all resident, occ=1)
#define THREADS_P 512
#define ROWS_CTA  16             // rows of W per CTA (128*16 = 2048)
#define K_EXT     2176           // 2048 (W) + 64 (W_in) + 64 zero pad = 128*17
#define K_SLICE   17             // k-elements per thread

// Device scratch (static __device__ globals only — no runtime alloc)
__device__ float        g_states[(size_t)T_STEPS * N_RES];  // 64 MB trace
__device__ float        g_s[2][N_RES];                      // double-buffered state
__device__ unsigned int g_flag[GRID_P * 32];                // per-CTA epoch, 128B apart

// ---------------------------------------------------------------------------
__global__ void init_kernel() {
    int i = blockIdx.x * blockDim.x + threadIdx.x;
    if (i < N_RES)  g_s[0][i] = 0.0f;
    if (i < GRID_P) g_flag[i * 32] = 0u;
}

// ---------------------------------------------------------------------------
__device__ __forceinline__ unsigned int ld_acq(const unsigned int* p) {
    unsigned int v;
    asm volatile("ld.acquire.gpu.global.u32 %0, [%1];" : "=r"(v) : "l"(p) : "memory");
    return v;
}
__device__ __forceinline__ void st_rel(unsigned int* p, unsigned int v) {
    asm volatile("st.release.gpu.global.u32 [%0], %1;" :: "l"(p), "r"(v) : "memory");
}

__global__ void __launch_bounds__(THREADS_P, 1)
reservoir_kernel(const float* __restrict__ u,
                 const float* __restrict__ noise,
                 const float* __restrict__ W_in,
                 const float* __restrict__ W)
{
    __shared__ float s_ext[2][K_EXT];    // double-buffered staged state + u + pad
    __shared__ float psum[ROWS_CTA][4];  // cross-warp partial sums

    const int tid  = threadIdx.x;
    const int lane = tid & 31;
    const int wid  = tid >> 5;            // 0..15
    const int wig  = wid & 3;             // warp within 4-warp row group
    const int kt   = tid & 127;           // k-lane 0..127
    const int rg   = tid >> 7;            // row group 0..3
    const int rbase = blockIdx.x * ROWS_CTA + rg * 4;

    // ---- W slice into registers: 4 rows x 17 k-elements per thread ----
    float w0[K_SLICE], w1[K_SLICE], w2[K_SLICE], w3[K_SLICE];
#pragma unroll
    for (int i = 0; i < K_SLICE; ++i) {
        const int k = kt + 128 * i;
        float a, b, c, d;
        if (k < N_RES) {
            a = W[(size_t)(rbase + 0) * N_RES + k];
            b = W[(size_t)(rbase + 1) * N_RES + k];
            c = W[(size_t)(rbase + 2) * N_RES + k];
            d = W[(size_t)(rbase + 3) * N_RES + k];
        } else if (k < N_RES + D_IN) {
            const int kk = k - N_RES;
            a = W_in[(rbase + 0) * D_IN + kk];
            b = W_in[(rbase + 1) * D_IN + kk];
            c = W_in[(rbase + 2) * D_IN + kk];
            d = W_in[(rbase + 3) * D_IN + kk];
        } else {
            a = b = c = d = 0.0f;
        }
        w0[i] = a; w1[i] = b; w2[i] = c; w3[i] = d;
    }

    // zero the pad region of both stage buffers once
    if (tid < 64) { s_ext[0][2112 + tid] = 0.0f; s_ext[1][2112 + tid] = 0.0f; }

    // ---- prefetch registers: u[0] (warp0 lanes 16-31), noise[0] (tid<16) ----
    const int myrow = blockIdx.x * ROWS_CTA + tid;   // valid for tid < 16
    float4 u_reg = make_float4(0.f, 0.f, 0.f, 0.f);
    if (wid == 0 && lane >= 16)
        u_reg = *(const float4*)&u[(lane - 16) * 4];
    float noise_reg = 0.0f;
    if (tid < 16)
        noise_reg = __ldcs(&noise[myrow]);

    // flag this warp polls: producers of its 128-element s-chunk
    const unsigned int* my_flag = &g_flag[(unsigned)(((wid << 3) + (lane & 7)) << 5)];

    for (int t = 0; t < T_STEPS; ++t) {
        const int buf  = t & 1;
        const int nbuf = buf ^ 1;

        // ---- per-chunk flag poll (skip t=0: init state is ready) ----
        if (t > 0) {
            const unsigned int need = (unsigned int)t;
            while (!__all_sync(0xffffffffu, ld_acq(my_flag) >= need)) { /* spin */ }
        }

        // ---- stage this warp's 128-element s chunk + u[t] ----
        {
            const int off = (wid << 7) + (lane << 2);
            const float4 sv = __ldcg((const float4*)&g_s[buf][off]);
            *(float4*)&s_ext[buf][off] = sv;
            if (wid == 0 && lane >= 16) {
                *(float4*)&s_ext[buf][2048 + ((lane - 16) << 2)] = u_reg;
                const int tn = (t + 1 < T_STEPS) ? t + 1 : t;
                u_reg = *(const float4*)&u[(size_t)tn * D_IN + ((lane - 16) << 2)];
            }
        }
        __syncthreads();   // bar #1: full s staged

        // ---- 4-row dot-product slice ----
        float a0 = 0.f, a1 = 0.f, a2 = 0.f, a3 = 0.f;
#pragma unroll
        for (int i = 0; i < K_SLICE; ++i) {
            const float x = s_ext[buf][kt + 128 * i];
            a0 = fmaf(w0[i], x, a0);
            a1 = fmaf(w1[i], x, a1);
            a2 = fmaf(w2[i], x, a2);
            a3 = fmaf(w3[i], x, a3);
        }
#pragma unroll
        for (int off = 16; off > 0; off >>= 1) {
            a0 += __shfl_xor_sync(0xffffffffu, a0, off);
            a1 += __shfl_xor_sync(0xffffffffu, a1, off);
            a2 += __shfl_xor_sync(0xffffffffu, a2, off);
            a3 += __shfl_xor_sync(0xffffffffu, a3, off);
        }
        if (lane == 0) {
            const int rl = (wid >> 2) * 4;
            psum[rl + 0][wig] = a0;
            psum[rl + 1][wig] = a1;
            psum[rl + 2][wig] = a2;
            psum[rl + 3][wig] = a3;
        }
        __syncthreads();   // bar #2: psums visible

        // ---- warp 0: finalize 16 rows, publish, release epoch flag ----
        // Other warps fall through directly to the next step's poll+stage
        // (they write the OTHER s_ext buffer; psum is rewritten only after
        //  bar #1 of step t+1, which warp 0 joins post-finalize).
        if (wid == 0) {
            float sn = 0.0f;
            if (lane < 16) {
                const float dot = psum[lane][0] + psum[lane][1]
                                + psum[lane][2] + psum[lane][3];
                const float ns  = tanhf(dot + NOISE_LVL * noise_reg);
                const float sp  = s_ext[buf][myrow];
                sn = (1.0f - LEAK) * sp + LEAK * ns;
                g_s[nbuf][myrow] = sn;
                g_states[(size_t)t * N_RES + myrow] = sn;
            }
            __syncwarp();
            if (lane == 0)
                st_rel(&g_flag[(unsigned)(blockIdx.x << 5)], (unsigned int)(t + 1));
            if (lane < 16) {   // prefetch next noise AFTER the release store
                const int tn = (t + 1 < T_STEPS) ? t + 1 : t;
                noise_reg = __ldcs(&noise[(size_t)tn * N_RES + myrow]);
            }
        }
    }
}

// ---------------------------------------------------------------------------
// Readout: out[T, 64] = states[T, 2048] @ w_out[64, 2048]^T + b_out
__global__ void __launch_bounds__(256)
readout_kernel(const float* __restrict__ wout,
               const float* __restrict__ bout,
               float* __restrict__ out)
{
    __shared__ float As[64][65];
    __shared__ float Bs[64][65];

    const int t0  = blockIdx.x * 64;
    const int tid = threadIdx.x;
    const int tx  = tid & 15;
    const int ty  = tid >> 4;

    float acc[4][4];
#pragma unroll
    for (int i = 0; i < 4; ++i)
#pragma unroll
        for (int j = 0; j < 4; ++j) acc[i][j] = 0.0f;

    for (int k0 = 0; k0 < N_RES; k0 += 64) {
#pragma unroll
        for (int i = tid; i < 1024; i += 256) {
            const int r  = i >> 4;
            const int c4 = (i & 15) * 4;
            const float4 v = *(const float4*)&g_states[(size_t)(t0 + r) * N_RES + k0 + c4];
            As[c4 + 0][r] = v.x; As[c4 + 1][r] = v.y;
            As[c4 + 2][r] = v.z; As[c4 + 3][r] = v.w;
            const float4 w = *(const float4*)&wout[(size_t)r * N_RES + k0 + c4];
            Bs[c4 + 0][r] = w.x; Bs[c4 + 1][r] = w.y;
            Bs[c4 + 2][r] = w.z; Bs[c4 + 3][r] = w.w;
        }
        __syncthreads();

#pragma unroll
        for (int kk = 0; kk < 64; ++kk) {
            float a[4], b[4];
#pragma unroll
            for (int j = 0; j < 4; ++j) { a[j] = As[kk][4 * ty + j]; b[j] = Bs[kk][4 * tx + j]; }
#pragma unroll
            for (int i = 0; i < 4; ++i)
#pragma unroll
                for (int j = 0; j < 4; ++j) acc[i][j] = fmaf(a[i], b[j], acc[i][j]);
        }
        __syncthreads();
    }

#pragma unroll
    for (int i = 0; i < 4; ++i)
#pragma unroll
        for (int j = 0; j < 4; ++j)
            out[(size_t)(t0 + 4 * ty + i) * D_OUT + 4 * tx + j] = acc[i][j] + bout[4 * tx + j];
}

// ---------------------------------------------------------------------------
extern "C" void kernel_launch(void* const* d_in, const int* in_sizes, int n_in,
                              void* d_out, int out_size)
{
    const float* u     = (const float*)d_in[0];
    const float* noise = (const float*)d_in[1];
    const float* W_in  = (const float*)d_in[2];
    const float* W     = (const float*)d_in[3];
    const float* w_out = (const float*)d_in[4];
    const float* b_out = (const float*)d_in[5];
    float*       out   = (float*)d_out;

    init_kernel<<<8, 256>>>();
    reservoir_kernel<<<GRID_P, THREADS_P>>>(u, noise, W_in, W);
    readout_kernel<<<T_STEPS / 64, 256>>>(w_out, b_out, out);
}